// round 8
// baseline (speedup 1.0000x reference)
#include <cuda_runtime.h>

// HierarchyInvertClassifier: out[b,k,h,w] = bias[k] + sum_{c in group k} w[c]*in[b,c,h,w]
// B=8, C=64, H=W=512, K=12. Groups are contiguous channel ranges (static).
//
// HBM-bound pure stream: 512 MiB read + 96 MiB write, zero reuse.
// R7: 64-thr blocks (fine drain granularity, helped R3->R4) + explicit
// load-all-then-FMA per group to structurally force front-batched LDGs
// (R5/R6 showed ptxas's 40-reg codegen shrinks batches and loses ~3-4%).
// Budget ~51 regs via launch_bounds(64,20).

#define HW   (512 * 512)
#define HW4  (HW / 4)         // 65536
#define CCH  64
#define KOUT 12

__constant__ int kGroupStart[KOUT + 1] = {0, 1, 4, 14, 20, 28, 38, 46, 52, 57, 59, 62, 64};

__global__ __launch_bounds__(64, 20)
void hier_invert_kernel(const float4* __restrict__ in4,
                        const float*  __restrict__ w,
                        const float*  __restrict__ bias,
                        float4* __restrict__ out4)
{
    __shared__ float sw[CCH];
    __shared__ float sb[KOUT];
    int t = threadIdx.x;
    sw[t] = w[t];
    if (t < KOUT) sb[t] = bias[t];
    __syncthreads();

    int idx  = blockIdx.x * blockDim.x + t;   // 0 .. 8*65536-1
    int bimg = idx >> 16;                     // image index (0..7)
    int pvec = idx & 0xFFFF;                  // float4 position within plane

    const float4* ip = in4 + ((long)bimg * CCH) * HW4 + pvec;
    float4*       op = out4 + ((long)bimg * KOUT) * HW4 + pvec;

    #pragma unroll
    for (int k = 0; k < KOUT; k++) {
        const int c0 = kGroupStart[k];
        const int c1 = kGroupStart[k + 1];
        const int gs = c1 - c0;               // compile-time constant per k

        // Phase 1: front-batch ALL of this group's loads (explicit array
        // forces the LDGs to issue before any consuming FMA).
        float4 v[10];                         // max group size
        #pragma unroll
        for (int j = 0; j < gs; j++)
            v[j] = __ldcs(ip + (long)(c0 + j) * HW4);

        // Phase 2: reduce.
        float bk = sb[k];
        float4 acc = make_float4(bk, bk, bk, bk);
        #pragma unroll
        for (int j = 0; j < gs; j++) {
            float wc = sw[c0 + j];
            acc.x = fmaf(wc, v[j].x, acc.x);
            acc.y = fmaf(wc, v[j].y, acc.y);
            acc.z = fmaf(wc, v[j].z, acc.z);
            acc.w = fmaf(wc, v[j].w, acc.w);
        }
        __stcs(op + (long)k * HW4, acc);
    }
}

extern "C" void kernel_launch(void* const* d_in, const int* in_sizes, int n_in,
                              void* d_out, int out_size)
{
    const float* pred_lr = (const float*)d_in[0];   // [8,64,512,512]
    const float* weights = (const float*)d_in[1];   // [64]
    const float* biases  = (const float*)d_in[2];   // [12]
    float* out = (float*)d_out;                     // [8,12,512,512]

    int total_vec = 8 * HW4;                        // 524288
    int threads = 64;
    int blocks  = total_vec / threads;              // 8192

    hier_invert_kernel<<<blocks, threads>>>(
        (const float4*)pred_lr, weights, biases, (float4*)out);
}

// round 9
// speedup vs baseline: 1.3370x; 1.3370x over previous
#include <cuda_runtime.h>

// HierarchyInvertClassifier: out[b,k,h,w] = bias[k] + sum_{c in group k} w[c]*in[b,c,h,w]
// B=8, C=64, H=W=512, K=12. Groups are contiguous channel ranges (static).
//
// HBM-bound pure stream: 512 MiB read + 96 MiB write, zero reuse.
// FINAL (= R4, the measured optimum of the config sweep):
//  - per-group accumulate+store (low liveness, lets ptxas front-batch the
//    group's LDG.128s for MLP)
//  - 128-thread blocks / 4096 blocks: fine drain-tail granularity
//  - launch_bounds(128,10): 48-reg budget -> fat load batches, no spills,
//    10 blocks/SM (40 warps)
//  - __ldcs/__stcs streaming hints (zero reuse)
// Sweep results: 60r/256t=101.2us, 48r/128t=96.4us, 40r=99.7-100.6us,
// explicit-array batching=local-mem spill 129us.

#define HW   (512 * 512)
#define HW4  (HW / 4)         // 65536
#define CCH  64
#define KOUT 12

__constant__ int kGroupStart[KOUT + 1] = {0, 1, 4, 14, 20, 28, 38, 46, 52, 57, 59, 62, 64};

__global__ __launch_bounds__(128, 10)
void hier_invert_kernel(const float4* __restrict__ in4,
                        const float*  __restrict__ w,
                        const float*  __restrict__ bias,
                        float4* __restrict__ out4)
{
    __shared__ float sw[CCH];
    __shared__ float sb[KOUT];
    int t = threadIdx.x;
    if (t < CCH)  sw[t] = w[t];
    if (t < KOUT) sb[t] = bias[t];
    __syncthreads();

    int idx  = blockIdx.x * blockDim.x + t;   // 0 .. 8*65536-1
    int bimg = idx >> 16;                     // image index (0..7)
    int pvec = idx & 0xFFFF;                  // float4 position within plane

    const float4* ip = in4 + ((long)bimg * CCH) * HW4 + pvec;
    float4*       op = out4 + ((long)bimg * KOUT) * HW4 + pvec;

    #pragma unroll
    for (int k = 0; k < KOUT; k++) {
        const int c0 = kGroupStart[k];
        const int c1 = kGroupStart[k + 1];
        float bk = sb[k];
        float4 acc = make_float4(bk, bk, bk, bk);
        #pragma unroll
        for (int c = c0; c < c1; c++) {
            float4 v  = __ldcs(ip + (long)c * HW4);
            float  wc = sw[c];
            acc.x = fmaf(wc, v.x, acc.x);
            acc.y = fmaf(wc, v.y, acc.y);
            acc.z = fmaf(wc, v.z, acc.z);
            acc.w = fmaf(wc, v.w, acc.w);
        }
        __stcs(op + (long)k * HW4, acc);
    }
}

extern "C" void kernel_launch(void* const* d_in, const int* in_sizes, int n_in,
                              void* d_out, int out_size)
{
    const float* pred_lr = (const float*)d_in[0];   // [8,64,512,512]
    const float* weights = (const float*)d_in[1];   // [64]
    const float* biases  = (const float*)d_in[2];   // [12]
    float* out = (float*)d_out;                     // [8,12,512,512]

    int total_vec = 8 * HW4;                        // 524288
    int threads = 128;
    int blocks  = total_vec / threads;              // 4096

    hier_invert_kernel<<<blocks, threads>>>(
        (const float4*)pred_lr, weights, biases, (float4*)out);
}